// round 2
// baseline (speedup 1.0000x reference)
#include <cuda_runtime.h>

// RecursiveFilter: y[0]=x[0]; y[n] = W*x[n] + (1-W)*y[n-1] along axis 2 (N)
// Shape: [B=4, C=3, N=32, H=256, W=256] fp32, contiguous.
// Lanes (b,c,h,w) are independent; recurrence only along N.
// One thread per float4 of (h,w); stride between frames is HW elements.
// Grid: x = hw4 tiles, y = bc  (avoids div/mod in the kernel).

#define FW 0.3f
#define FW1 0.7f

static constexpr int Ndim = 32;
static constexpr int HW   = 256 * 256;   // elements per frame per (b,c)
static constexpr int HW4  = HW / 4;      // 16384 float4 per frame
static constexpr int BC   = 4 * 3;

__global__ __launch_bounds__(256)
void recursive_filter_kernel(const float4* __restrict__ x,
                             float4* __restrict__ y)
{
    int hw4 = blockIdx.x * blockDim.x + threadIdx.x;   // 0..HW4-1 (exact)
    int bc  = blockIdx.y;                              // 0..BC-1

    // float4-unit offset of (bc, n=0, hw4)
    long base = (long)bc * Ndim * HW4 + hw4;

    float4 c = x[base];
    y[base] = c;

#pragma unroll
    for (int n = 1; n < Ndim; ++n) {
        long off = base + (long)n * HW4;
        float4 v = x[off];
        c.x = FW * v.x + FW1 * c.x;
        c.y = FW * v.y + FW1 * c.y;
        c.z = FW * v.z + FW1 * c.z;
        c.w = FW * v.w + FW1 * c.w;
        y[off] = c;
    }
}

extern "C" void kernel_launch(void* const* d_in, const int* in_sizes, int n_in,
                              void* d_out, int out_size)
{
    const float4* x = (const float4*)d_in[0];
    float4* y = (float4*)d_out;

    dim3 grid(HW4 / 256, BC, 1);   // (64, 12) = 768 CTAs
    recursive_filter_kernel<<<grid, 256>>>(x, y);
}